// round 14
// baseline (speedup 1.0000x reference)
#include <cuda_runtime.h>
#include <cuda_bf16.h>
#include <cuda_fp16.h>
#include <cstdint>
#include <math.h>

#define NNODES 20000
#define KNBR 16
#define DDIM 128
#define NR (NNODES * KNBR)   /* 320000 pair rows */
#define SAS 20               /* padded smem row stride in uint32 */
#define DSMEM 81920          /* 2 stages x 4 planes x 128 x SAS x 4B */
#define LNSMEM (128 * 132 * 4)

// ======================= device scratch (allocation-free) =======================
__device__ __nv_bfloat16 g_A1h[(size_t)NR * 256];
__device__ __nv_bfloat16 g_A1l[(size_t)NR * 256];
__device__ __half        g_S[(size_t)NR * 256];       // fp16 sigmoid gates (si | so)
__device__ float         g_upre[(size_t)NR * 128];    // u pre-LN (pair); reused for local tail
__device__ __nv_bfloat16 g_Hh[(size_t)NR * 256];
__device__ __nv_bfloat16 g_Hl[(size_t)NR * 256];
__device__ float         g_Cc[(size_t)NNODES * 512];  // interleaved (g,v) per node
__device__ float         g_inc[NNODES * DDIM];
__device__ float         g_outg[NNODES * DDIM];
__device__ __nv_bfloat16 g_Lh[NNODES * DDIM], g_Ll[NNODES * DDIM];
__device__ __nv_bfloat16 g_X2h[NNODES * 384], g_X2l[NNODES * 384];
__device__ __nv_bfloat16 g_X3h[(size_t)NNODES * 256], g_X3l[(size_t)NNODES * 256];
// weights, split bf16, stored [n][k] (K-major rows); MLP hidden weights INTERLEAVED: n=2j+s (s=0 gate, 1 value)
__device__ __nv_bfloat16 gW13h[512 * 256], gW13l[512 * 256];
__device__ __nv_bfloat16 gWch[512 * 128],  gWcl[512 * 128];
__device__ __nv_bfloat16 gBo1h[128 * 256], gBo1l[128 * 256];
__device__ __nv_bfloat16 gBioh[256 * 128], gBiol[256 * 128];
__device__ __nv_bfloat16 gB2h[512 * 384],  gB2l[512 * 384];
__device__ __nv_bfloat16 gBo2h[128 * 256], gBo2l[128 * 256];

// ======================= helpers =======================
__device__ __forceinline__ uint32_t smem_to_u32(const void* p) {
    uint32_t a;
    asm("{ .reg .u64 t; cvta.to.shared.u64 t, %1; cvt.u32.u64 %0, t; }" : "=r"(a) : "l"(p));
    return a;
}
__device__ __forceinline__ float gelu_tanh(float x) {
    float x3 = x * x * x;
    return 0.5f * x * (1.0f + tanhf(0.7978845608028654f * (x + 0.044715f * x3)));
}
__device__ __forceinline__ float sigm(float x) { return 1.0f / (1.0f + expf(-x)); }
__device__ __forceinline__ void split_bf16(float v, __nv_bfloat16& h, __nv_bfloat16& l) {
    h = __float2bfloat16(v);
    l = __float2bfloat16(v - __bfloat162float(h));
}
__device__ __forceinline__ void mma16816(float* c, const uint32_t* a, uint32_t b0, uint32_t b1) {
    asm volatile(
        "mma.sync.aligned.m16n8k16.row.col.f32.bf16.bf16.f32 "
        "{%0,%1,%2,%3}, {%4,%5,%6,%7}, {%8,%9}, {%0,%1,%2,%3};"
        : "+f"(c[0]), "+f"(c[1]), "+f"(c[2]), "+f"(c[3])
        : "r"(a[0]), "r"(a[1]), "r"(a[2]), "r"(a[3]), "r"(b0), "r"(b1));
}
__device__ __forceinline__ void ldsm4(uint32_t& r0, uint32_t& r1, uint32_t& r2, uint32_t& r3, uint32_t addr) {
    asm volatile("ldmatrix.sync.aligned.m8n8.x4.shared.b16 {%0,%1,%2,%3}, [%4];"
                 : "=r"(r0), "=r"(r1), "=r"(r2), "=r"(r3) : "r"(addr));
}
__device__ __forceinline__ void cp16(uint32_t dst, const void* src) {
    asm volatile("cp.async.cg.shared.global [%0], [%1], 16;" :: "r"(dst), "l"(src));
}
#define CP_COMMIT() asm volatile("cp.async.commit_group;" ::: "memory")
#define CP_WAIT(n)  asm volatile("cp.async.wait_group %0;" :: "n"(n) : "memory")

// ======================= split-bf16 GEMM (mma.sync + ldmatrix + cp.async) ==========
// C[m0:+128, n0:+128] = (Ah+Al)[M,K] @ (Bh+Bl)[N,K]^T; 3-term split AhBh+AhBl+AlBh.
// MODE 0: fp32 out.  MODE 1: sigmoid -> fp16 out (C reinterpreted as __half*, ldc in half units).
// MODE 2: fused gated-MLP epilogue (interleaved g|v cols -> split bf16 Oh/Ol, 256-wide).
// Grid: n fastest (blockIdx.x = n-block) -> consecutive CTAs share the A tile in L2.
template <int MODE>
__global__ void __launch_bounds__(256)
gemm_kernel(const __nv_bfloat16* __restrict__ Ah, const __nv_bfloat16* __restrict__ Al,
            int lda, int M, int K,
            const __nv_bfloat16* __restrict__ Bh, const __nv_bfloat16* __restrict__ Bl,
            float* __restrict__ C, int ldc,
            const float* __restrict__ Cc,
            const float* __restrict__ bgp, const float* __restrict__ bvp,
            __nv_bfloat16* __restrict__ Oh, __nv_bfloat16* __restrict__ Ol)
{
    extern __shared__ __align__(16) uint32_t dynsmem[];
    const uint32_t sbase = smem_to_u32(dynsmem);
    const int t = threadIdx.x, wid = t >> 5, lane = t & 31;
    const int lr = lane >> 2, lc = lane & 3;
    const int wm = wid & 3, wn = wid >> 2;
    const int n0 = blockIdx.x * 128, m0 = blockIdx.y * 128;   // n fastest

    float acc[2][8][4] = {};
    const int nch = K >> 5;

    auto issue = [&](int kc, int st) {
        uint32_t sb = sbase + (uint32_t)st * 40960u;
        #pragma unroll
        for (int i = t; i < 1024; i += 256) {     // A: planes h,l (128 rows x 32 bf16)
            int p = i >> 9, e = i & 511, r = e >> 2, q = e & 3;
            int row = m0 + r; if (row >= M) row = M - 1;   // clamp; rows >= M never written
            cp16(sb + (uint32_t)(p * 10240 + (r * SAS + q * 4) * 4),
                 (p ? Al : Ah) + (size_t)row * lda + kc * 32 + q * 8);
        }
        #pragma unroll
        for (int i = t; i < 1024; i += 256) {     // B: planes h,l
            int p = i >> 9, e = i & 511, r = e >> 2, q = e & 3;
            cp16(sb + (uint32_t)(20480 + p * 10240 + (r * SAS + q * 4) * 4),
                 (p ? Bl : Bh) + (size_t)(n0 + r) * K + kc * 32 + q * 8);
        }
    };

    issue(0, 0); CP_COMMIT();

    const int aRowL = lane & 15;
    const uint32_t aOffB = (uint32_t)((lane >> 4) << 4);
    const int bRowL = (lane & 7) + ((lane >> 4) << 3);
    const uint32_t bOffB = (uint32_t)(((lane >> 3) & 1) << 4);

    for (int kc = 0; kc < nch; kc++) {
        int st = kc & 1;
        if (kc + 1 < nch) { issue(kc + 1, st ^ 1); CP_COMMIT(); CP_WAIT(1); }
        else              { CP_WAIT(0); }
        __syncthreads();

        uint32_t stb = sbase + (uint32_t)st * 40960u;
        #pragma unroll
        for (int s = 0; s < 2; s++) {
            uint32_t ah[2][4], al[2][4];
            #pragma unroll
            for (int mf = 0; mf < 2; mf++) {
                uint32_t ra = (uint32_t)(((wm * 32 + mf * 16 + aRowL) * SAS + s * 8) * 4) + aOffB;
                ldsm4(ah[mf][0], ah[mf][1], ah[mf][2], ah[mf][3], stb + ra);
                ldsm4(al[mf][0], al[mf][1], al[mf][2], al[mf][3], stb + 10240 + ra);
            }
            #pragma unroll
            for (int nfp = 0; nfp < 4; nfp++) {
                uint32_t rb = (uint32_t)(((wn * 64 + nfp * 16 + bRowL) * SAS + s * 8) * 4) + bOffB;
                uint32_t bh[4], bl[4];
                ldsm4(bh[0], bh[1], bh[2], bh[3], stb + 20480 + rb);
                ldsm4(bl[0], bl[1], bl[2], bl[3], stb + 30720 + rb);
                #pragma unroll
                for (int mf = 0; mf < 2; mf++) {
                    mma16816(acc[mf][2 * nfp],     ah[mf], bh[0], bh[1]);
                    mma16816(acc[mf][2 * nfp],     ah[mf], bl[0], bl[1]);
                    mma16816(acc[mf][2 * nfp],     al[mf], bh[0], bh[1]);
                    mma16816(acc[mf][2 * nfp + 1], ah[mf], bh[2], bh[3]);
                    mma16816(acc[mf][2 * nfp + 1], ah[mf], bl[2], bl[3]);
                    mma16816(acc[mf][2 * nfp + 1], al[mf], bh[2], bh[3]);
                }
            }
        }
        __syncthreads();
    }

    // ---- epilogue ----
    #pragma unroll
    for (int mf = 0; mf < 2; mf++) {
        int r0 = m0 + wm * 32 + mf * 16 + lr;
        int r1 = r0 + 8;
        #pragma unroll
        for (int nf = 0; nf < 8; nf++) {
            int col = n0 + wn * 64 + nf * 8 + 2 * lc;
            float c0 = acc[mf][nf][0], c1 = acc[mf][nf][1];
            float c2 = acc[mf][nf][2], c3 = acc[mf][nf][3];
            if (MODE == 0) {
                if (r0 < M) *reinterpret_cast<float2*>(C + (size_t)r0 * ldc + col) = make_float2(c0, c1);
                if (r1 < M) *reinterpret_cast<float2*>(C + (size_t)r1 * ldc + col) = make_float2(c2, c3);
            } else if (MODE == 1) {
                __half* Ch = reinterpret_cast<__half*>(C);
                if (r0 < M) *reinterpret_cast<__half2*>(Ch + (size_t)r0 * ldc + col) =
                    __floats2half2_rn(sigm(c0), sigm(c1));
                if (r1 < M) *reinterpret_cast<__half2*>(Ch + (size_t)r1 * ldc + col) =
                    __floats2half2_rn(sigm(c2), sigm(c3));
            } else {
                int j = col >> 1;
                float bgj = bgp[j], bvj = bvp[j];
                if (r0 < M) {
                    float cg = 0.f, cv = 0.f;
                    if (Cc) { float2 cc = *reinterpret_cast<const float2*>(Cc + (size_t)(r0 >> 4) * 512 + col); cg = cc.x; cv = cc.y; }
                    float h = gelu_tanh(c0 + cg + bgj) * (c1 + cv + bvj);
                    split_bf16(h, Oh[(size_t)r0 * 256 + j], Ol[(size_t)r0 * 256 + j]);
                }
                if (r1 < M) {
                    float cg = 0.f, cv = 0.f;
                    if (Cc) { float2 cc = *reinterpret_cast<const float2*>(Cc + (size_t)(r1 >> 4) * 512 + col); cg = cc.x; cv = cc.y; }
                    float h = gelu_tanh(c2 + cg + bgj) * (c3 + cv + bvj);
                    split_bf16(h, Oh[(size_t)r1 * 256 + j], Ol[(size_t)r1 * 256 + j]);
                }
            }
        }
    }
}

// ======================= fused LN + messages (no GEMM inside) ==========
// One CTA = 128 pair rows = 8 complete nodes; pu staged in smem, never in HBM.
__global__ void __launch_bounds__(256)
ln_msg_kernel(const float* __restrict__ upre, const float* __restrict__ pair,
              const __half* __restrict__ S,
              const int* __restrict__ nbrs, const float* __restrict__ mask,
              const float* __restrict__ gp, const float* __restrict__ bp,
              float* __restrict__ out)
{
    extern __shared__ float spu[];   // 128 rows x 132 floats
    __shared__ int   snbr[128];
    __shared__ float sval[128];
    const int t = threadIdx.x, wid = t >> 5, lane = t & 31;
    const int base = blockIdx.x * 128;

    if (t < 128) {
        int nb = nbrs[base + t];
        int nbw = (nb < 0) ? nb + NNODES : nb;
        snbr[t] = nbw;
        sval[t] = (nb != -1 && mask[nbw] > 0.0f) ? 1.0f : 0.0f;
    }

    // LN per row (8 warps x 16 rows)
    for (int r = wid * 16; r < wid * 16 + 16; r++) {
        size_t grow = (size_t)(base + r) * 128;
        float v[4], s = 0.f, sq = 0.f;
        #pragma unroll
        for (int j = 0; j < 4; j++) {
            v[j] = upre[grow + lane + j * 32];
            s += v[j]; sq += v[j] * v[j];
        }
        #pragma unroll
        for (int o = 16; o > 0; o >>= 1) {
            s  += __shfl_xor_sync(0xffffffffu, s, o);
            sq += __shfl_xor_sync(0xffffffffu, sq, o);
        }
        float m = s * (1.0f / 128.0f);
        float var = sq * (1.0f / 128.0f) - m * m;
        float rstd = rsqrtf(var + 1e-5f);
        #pragma unroll
        for (int j = 0; j < 4; j++) {
            int col = lane + j * 32;
            float pu = (v[j] - m) * rstd * gp[col] + bp[col];
            spu[r * 132 + col] = pu;
            out[(size_t)NNODES * 128 + grow + col] = pair[grow + col] + pu;
        }
    }
    __syncthreads();

    // messages: incoming (CTA-local sum) + outgoing atomic scatter
    int c = t & 127, halfid = t >> 7;
    for (int nl = halfid * 4; nl < halfid * 4 + 4; nl++) {
        float inc = 0.0f;
        #pragma unroll
        for (int r = 0; r < KNBR; r++) {
            int row = nl * 16 + r;
            if (sval[row] > 0.0f) {
                float pu = spu[row * 132 + c];
                float si = __half2float(S[(size_t)(base + row) * 256 + c]);
                float so = __half2float(S[(size_t)(base + row) * 256 + 128 + c]);
                inc += si * pu;
                atomicAdd(&g_outg[snbr[row] * 128 + c], so * pu);
            }
        }
        g_inc[(blockIdx.x * 8 + nl) * 128 + c] = inc;
    }
}

// ======================= elementwise / prep kernels =======================
__global__ void zero_out_kernel() {
    int i = blockIdx.x * blockDim.x + threadIdx.x;
    if (i < NNODES * DDIM) g_outg[i] = 0.0f;
}

__global__ void prep_weights_kernel(
    const float* __restrict__ Wg1, const float* __restrict__ Wv1,
    const float* __restrict__ Wo1, const float* __restrict__ Win,
    const float* __restrict__ Wou, const float* __restrict__ Wg2,
    const float* __restrict__ Wv2, const float* __restrict__ Wo2)
{
    int i = blockIdx.x * blockDim.x + threadIdx.x;
    int stride = gridDim.x * blockDim.x;
    for (int x = i; x < 512 * 256; x += stride) {   // W13i
        int n = x >> 8, k = x & 255;
        int j = n >> 1;
        const float* W = (n & 1) ? Wv1 : Wg1;
        int krow = (k < 128) ? k : (256 + (k - 128));
        split_bf16(W[krow * 256 + j], gW13h[x], gW13l[x]);
    }
    for (int x = i; x < 512 * 128; x += stride) {   // Wceni
        int n = x >> 7, k = x & 127;
        int j = n >> 1;
        const float* W = (n & 1) ? Wv1 : Wg1;
        split_bf16(W[(128 + k) * 256 + j], gWch[x], gWcl[x]);
    }
    for (int x = i; x < 128 * 256; x += stride) {   // Bo1
        int n = x >> 8, k = x & 255;
        split_bf16(Wo1[k * 128 + n], gBo1h[x], gBo1l[x]);
    }
    for (int x = i; x < 256 * 128; x += stride) {   // Bio
        int n = x >> 7, k = x & 127;
        const float* W = (n < 128) ? Win : Wou;
        split_bf16(W[k * 128 + (n & 127)], gBioh[x], gBiol[x]);
    }
    for (int x = i; x < 512 * 384; x += stride) {   // B2i
        int n = x / 384, k = x % 384;
        int j = n >> 1;
        const float* W = (n & 1) ? Wv2 : Wg2;
        split_bf16(W[k * 256 + j], gB2h[x], gB2l[x]);
    }
    for (int x = i; x < 128 * 256; x += stride) {   // Bo2
        int n = x >> 8, k = x & 255;
        split_bf16(Wo2[k * 128 + n], gBo2h[x], gBo2l[x]);
    }
}

__global__ void prep_A1_kernel(const float* __restrict__ pair, const float* __restrict__ local,
                               const int* __restrict__ nbrs)
{
    size_t i = (size_t)blockIdx.x * blockDim.x + threadIdx.x;
    if (i >= (size_t)NR * 256) return;
    int c = (int)(i & 255);
    size_t r = i >> 8;
    float v;
    if (c < 128) {
        v = pair[r * 128 + c];
    } else {
        int nb = nbrs[r];
        if (nb < 0) nb += NNODES;   // python wrap for -1
        v = local[(size_t)nb * 128 + (c - 128)];
    }
    split_bf16(v, g_A1h[i], g_A1l[i]);
}

__global__ void prep_L_kernel(const float* __restrict__ local) {
    int i = blockIdx.x * blockDim.x + threadIdx.x;
    if (i < NNODES * DDIM) split_bf16(local[i], g_Lh[i], g_Ll[i]);
}

__global__ void prep_X2_kernel(const float* __restrict__ local) {
    int i = blockIdx.x * blockDim.x + threadIdx.x;
    if (i >= NNODES * 384) return;
    int k = i % 384;
    int r = i / 384;
    float v;
    if (k < 128)       v = local[(size_t)r * 128 + k];
    else if (k < 256)  v = g_inc[r * 128 + (k - 128)];
    else               v = g_outg[r * 128 + (k - 256)];
    split_bf16(v, g_X2h[i], g_X2l[i]);
}

__global__ void ln_local_kernel(const float* __restrict__ local, const float* __restrict__ bo,
                                const float* __restrict__ gl, const float* __restrict__ bl,
                                float* __restrict__ out)
{
    int row = blockIdx.x * 8 + (threadIdx.x >> 5);
    int lane = threadIdx.x & 31;
    if (row >= NNODES) return;
    const float* up = g_upre + (size_t)row * 128;
    float v[4], s = 0.0f, sq = 0.0f;
    #pragma unroll
    for (int j = 0; j < 4; j++) {
        int col = lane + j * 32;
        v[j] = up[col] + bo[col];
        s += v[j]; sq += v[j] * v[j];
    }
    #pragma unroll
    for (int o = 16; o > 0; o >>= 1) {
        s  += __shfl_xor_sync(0xffffffffu, s, o);
        sq += __shfl_xor_sync(0xffffffffu, sq, o);
    }
    float m = s * (1.0f / 128.0f);
    float var = sq * (1.0f / 128.0f) - m * m;
    float rstd = rsqrtf(var + 1e-5f);
    #pragma unroll
    for (int j = 0; j < 4; j++) {
        int col = lane + j * 32;
        float lu = (v[j] - m) * rstd * gl[col] + bl[col];
        out[(size_t)row * 128 + col] = local[(size_t)row * 128 + col] + lu;
    }
}

// u_pre for the pair path includes +bo1 inside ln_msg?  No: bo is added pre-LN.
// We add bo1 into upre during the u GEMM by folding it via a tiny kernel-free trick:
// keep the R13 semantics: LN reads upre + bo.  ln_msg adds bo via gp/bp path — must add bo first.
// To keep arithmetic identical, fold bo into upre with an epilogue-free approach:
// ln_msg_kernel includes +bo? — handled: we pass bo through and add before stats.
__global__ void add_bias_kernel(float* __restrict__ buf, const float* __restrict__ bo, size_t rows) {
    size_t i = (size_t)blockIdx.x * blockDim.x + threadIdx.x;
    if (i >= rows * 128) return;
    buf[i] += bo[i & 127];
}

// ======================= launch =======================
extern "C" void kernel_launch(void* const* d_in, const int* in_sizes, int n_in,
                              void* d_out, int out_size)
{
    const float* local = (const float*)d_in[0];
    const float* pair  = (const float*)d_in[1];
    const int*   nbrs  = (const int*)  d_in[2];
    const float* mask  = (const float*)d_in[3];
    const float* Wg1 = (const float*)d_in[4];
    const float* bg1 = (const float*)d_in[5];
    const float* Wv1 = (const float*)d_in[6];
    const float* bv1 = (const float*)d_in[7];
    const float* Wo1 = (const float*)d_in[8];
    const float* bo1 = (const float*)d_in[9];
    const float* gp  = (const float*)d_in[10];
    const float* bp  = (const float*)d_in[11];
    const float* Win = (const float*)d_in[12];
    const float* Wou = (const float*)d_in[13];
    const float* Wg2 = (const float*)d_in[14];
    const float* bg2 = (const float*)d_in[15];
    const float* Wv2 = (const float*)d_in[16];
    const float* bv2 = (const float*)d_in[17];
    const float* Wo2 = (const float*)d_in[18];
    const float* bo2 = (const float*)d_in[19];
    const float* gl  = (const float*)d_in[20];
    const float* bl  = (const float*)d_in[21];
    float* out = (float*)d_out;

    cudaFuncSetAttribute(gemm_kernel<0>, cudaFuncAttributeMaxDynamicSharedMemorySize, DSMEM);
    cudaFuncSetAttribute(gemm_kernel<1>, cudaFuncAttributeMaxDynamicSharedMemorySize, DSMEM);
    cudaFuncSetAttribute(gemm_kernel<2>, cudaFuncAttributeMaxDynamicSharedMemorySize, DSMEM);
    cudaFuncSetAttribute(ln_msg_kernel, cudaFuncAttributeMaxDynamicSharedMemorySize, LNSMEM);

    float *gupre, *gcc;
    cudaGetSymbolAddress((void**)&gupre, g_upre);
    cudaGetSymbolAddress((void**)&gcc,   g_Cc);
    __half* gsh;
    cudaGetSymbolAddress((void**)&gsh, g_S);
    __nv_bfloat16 *a1h, *a1l, *hh, *hl, *lh, *ll, *x2h, *x2l, *x3h, *x3l;
    cudaGetSymbolAddress((void**)&a1h, g_A1h); cudaGetSymbolAddress((void**)&a1l, g_A1l);
    cudaGetSymbolAddress((void**)&hh,  g_Hh);  cudaGetSymbolAddress((void**)&hl,  g_Hl);
    cudaGetSymbolAddress((void**)&lh,  g_Lh);  cudaGetSymbolAddress((void**)&ll,  g_Ll);
    cudaGetSymbolAddress((void**)&x2h, g_X2h); cudaGetSymbolAddress((void**)&x2l, g_X2l);
    cudaGetSymbolAddress((void**)&x3h, g_X3h); cudaGetSymbolAddress((void**)&x3l, g_X3l);
    __nv_bfloat16 *w13h, *w13l, *wch, *wcl, *bo1h, *bo1l, *bioh, *biol, *b2h, *b2l, *bo2h, *bo2l;
    cudaGetSymbolAddress((void**)&w13h, gW13h); cudaGetSymbolAddress((void**)&w13l, gW13l);
    cudaGetSymbolAddress((void**)&wch,  gWch);  cudaGetSymbolAddress((void**)&wcl,  gWcl);
    cudaGetSymbolAddress((void**)&bo1h, gBo1h); cudaGetSymbolAddress((void**)&bo1l, gBo1l);
    cudaGetSymbolAddress((void**)&bioh, gBioh); cudaGetSymbolAddress((void**)&biol, gBiol);
    cudaGetSymbolAddress((void**)&b2h,  gB2h);  cudaGetSymbolAddress((void**)&b2l,  gB2l);
    cudaGetSymbolAddress((void**)&bo2h, gBo2h); cudaGetSymbolAddress((void**)&bo2l, gBo2l);

    // 1) prep
    zero_out_kernel<<<(NNODES * DDIM + 255) / 256, 256>>>();
    prep_weights_kernel<<<512, 256>>>(Wg1, Wv1, Wo1, Win, Wou, Wg2, Wv2, Wo2);
    prep_A1_kernel<<<(int)(((size_t)NR * 256 + 255) / 256), 256>>>(pair, local, nbrs);
    prep_L_kernel<<<(NNODES * DDIM + 255) / 256, 256>>>(local);

    // 2) Cc = local @ Wceni : [20000,128]x[128,512]
    gemm_kernel<0><<<dim3(4, 157), 256, DSMEM>>>(lh, ll, 128, NNODES, 128, wch, wcl,
                                                 gcc, 512, nullptr, nullptr, nullptr, nullptr, nullptr);
    // 3) H = gelu(A1@W13i + Cc + bg) * (… + bv) -> split bf16 Hh/Hl
    gemm_kernel<2><<<dim3(4, 2500), 256, DSMEM>>>(a1h, a1l, 256, NR, 256, w13h, w13l,
                                                  nullptr, 0, gcc, bg1, bv1, hh, hl);
    // 4) u_pre = H @ Bo1 : [320000,256]x[256,128] -> g_upre
    gemm_kernel<0><<<dim3(1, 2500), 256, DSMEM>>>(hh, hl, 256, NR, 256, bo1h, bo1l,
                                                  gupre, 128, nullptr, nullptr, nullptr, nullptr, nullptr);
    // 4b) fold +bo1 into u_pre (pre-LN bias, keeps arithmetic identical to reference)
    add_bias_kernel<<<(int)(((size_t)NR * 128 + 255) / 256), 256>>>(gupre, bo1, NR);
    // 5) gates S = sigmoid(A1.pair @ [Win||Wou]) -> fp16 g_S
    gemm_kernel<1><<<dim3(2, 2500), 256, DSMEM>>>(a1h, a1l, 256, NR, 128, bioh, biol,
                                                  (float*)gsh, 256, nullptr, nullptr, nullptr, nullptr, nullptr);
    // 6) fused LN + pair residual + messages (pu stays in smem)
    ln_msg_kernel<<<2500, 256, LNSMEM>>>(gupre, pair, gsh, nbrs, mask, gp, bp, out);
    // 7) local features
    prep_X2_kernel<<<(NNODES * 384 + 255) / 256, 256>>>(local);
    // 8) X3 = fused local MLP hidden : [20000,384]x[384,512]
    gemm_kernel<2><<<dim3(4, 157), 256, DSMEM>>>(x2h, x2l, 384, NNODES, 384, b2h, b2l,
                                                 nullptr, 0, nullptr, bg2, bv2, x3h, x3l);
    // 9) u2_pre = X3 @ Bo2 -> g_upre (reuse)
    gemm_kernel<0><<<dim3(1, 157), 256, DSMEM>>>(x3h, x3l, 256, NNODES, 256, bo2h, bo2l,
                                                 gupre, 128, nullptr, nullptr, nullptr, nullptr, nullptr);
    // 10) LN local + residual local output (adds bo2 inside)
    ln_local_kernel<<<(NNODES + 7) / 8, 256>>>(local, bo2, gl, bl, out);
}

// round 16
// speedup vs baseline: 1.1031x; 1.1031x over previous
#include <cuda_runtime.h>
#include <cuda_bf16.h>
#include <cuda_fp16.h>
#include <cstdint>
#include <math.h>

#define NNODES 20000
#define KNBR 16
#define DDIM 128
#define NR (NNODES * KNBR)   /* 320000 pair rows */
#define SAS 20               /* padded smem row stride in uint32 */
#define DSMEM 81920          /* 2 stages x 4 planes x 128 x SAS x 4B */

// ======================= device scratch (allocation-free) =======================
__device__ __nv_bfloat16 g_A1h[(size_t)NR * 256];
__device__ __nv_bfloat16 g_A1l[(size_t)NR * 256];
__device__ __half        g_S[(size_t)NR * 256];       // fp16 sigmoid gates (si | so)
__device__ float         g_upre[(size_t)NR * 128];    // u pre-LN (pair); reused by local tail
__device__ float         g_pu[(size_t)NR * 128];
__device__ __nv_bfloat16 g_Hh[(size_t)NR * 256];
__device__ __nv_bfloat16 g_Hl[(size_t)NR * 256];
__device__ float         g_Cc[(size_t)NNODES * 512];  // interleaved (g,v) per node
__device__ float         g_inc[NNODES * DDIM];
__device__ float         g_outg[NNODES * DDIM];
__device__ __nv_bfloat16 g_Lh[NNODES * DDIM], g_Ll[NNODES * DDIM];
__device__ __nv_bfloat16 g_X2h[NNODES * 384], g_X2l[NNODES * 384];
__device__ __nv_bfloat16 g_X3h[(size_t)NNODES * 256], g_X3l[(size_t)NNODES * 256];
// weights, split bf16, stored [n][k] (K-major rows); MLP hidden weights INTERLEAVED: n=2j+s (s=0 gate, 1 value)
__device__ __nv_bfloat16 gW13h[512 * 256], gW13l[512 * 256];
__device__ __nv_bfloat16 gWch[512 * 128],  gWcl[512 * 128];
__device__ __nv_bfloat16 gBo1h[128 * 256], gBo1l[128 * 256];
__device__ __nv_bfloat16 gBioh[256 * 128], gBiol[256 * 128];
__device__ __nv_bfloat16 gB2h[512 * 384],  gB2l[512 * 384];
__device__ __nv_bfloat16 gBo2h[128 * 256], gBo2l[128 * 256];

// ======================= helpers =======================
__device__ __forceinline__ uint32_t smem_to_u32(const void* p) {
    uint32_t a;
    asm("{ .reg .u64 t; cvta.to.shared.u64 t, %1; cvt.u32.u64 %0, t; }" : "=r"(a) : "l"(p));
    return a;
}
__device__ __forceinline__ float gelu_tanh(float x) {
    float x3 = x * x * x;
    return 0.5f * x * (1.0f + tanhf(0.7978845608028654f * (x + 0.044715f * x3)));
}
__device__ __forceinline__ float sigm(float x) { return 1.0f / (1.0f + expf(-x)); }
__device__ __forceinline__ void split_bf16(float v, __nv_bfloat16& h, __nv_bfloat16& l) {
    h = __float2bfloat16(v);
    l = __float2bfloat16(v - __bfloat162float(h));
}
__device__ __forceinline__ void mma16816(float* c, const uint32_t* a, uint32_t b0, uint32_t b1) {
    asm volatile(
        "mma.sync.aligned.m16n8k16.row.col.f32.bf16.bf16.f32 "
        "{%0,%1,%2,%3}, {%4,%5,%6,%7}, {%8,%9}, {%0,%1,%2,%3};"
        : "+f"(c[0]), "+f"(c[1]), "+f"(c[2]), "+f"(c[3])
        : "r"(a[0]), "r"(a[1]), "r"(a[2]), "r"(a[3]), "r"(b0), "r"(b1));
}
__device__ __forceinline__ void ldsm4(uint32_t& r0, uint32_t& r1, uint32_t& r2, uint32_t& r3, uint32_t addr) {
    asm volatile("ldmatrix.sync.aligned.m8n8.x4.shared.b16 {%0,%1,%2,%3}, [%4];"
                 : "=r"(r0), "=r"(r1), "=r"(r2), "=r"(r3) : "r"(addr));
}
__device__ __forceinline__ void cp16(uint32_t dst, const void* src) {
    asm volatile("cp.async.cg.shared.global [%0], [%1], 16;" :: "r"(dst), "l"(src));
}
#define CP_COMMIT() asm volatile("cp.async.commit_group;" ::: "memory")
#define CP_WAIT(n)  asm volatile("cp.async.wait_group %0;" :: "n"(n) : "memory")

// ======================= split-bf16 GEMM (mma.sync + ldmatrix + cp.async) ==========
// C[m0:+128, n0:+128] = (Ah+Al)[M,K] @ (Bh+Bl)[N,K]^T; 3-term split AhBh+AhBl+AlBh.
// MODE 0: fp32 out.  MODE 1: sigmoid -> fp16 out (C as __half*, ldc in half units).
// MODE 2: fused gated-MLP epilogue (interleaved g|v cols -> split bf16 Oh/Ol, 256-wide).
// Grid: n fastest (blockIdx.x = n-block) -> consecutive CTAs share the A tile in L2.
template <int MODE>
__global__ void __launch_bounds__(256)
gemm_kernel(const __nv_bfloat16* __restrict__ Ah, const __nv_bfloat16* __restrict__ Al,
            int lda, int M, int K,
            const __nv_bfloat16* __restrict__ Bh, const __nv_bfloat16* __restrict__ Bl,
            float* __restrict__ C, int ldc,
            const float* __restrict__ Cc,
            const float* __restrict__ bgp, const float* __restrict__ bvp,
            __nv_bfloat16* __restrict__ Oh, __nv_bfloat16* __restrict__ Ol)
{
    extern __shared__ __align__(16) uint32_t dynsmem[];
    const uint32_t sbase = smem_to_u32(dynsmem);
    const int t = threadIdx.x, wid = t >> 5, lane = t & 31;
    const int lr = lane >> 2, lc = lane & 3;
    const int wm = wid & 3, wn = wid >> 2;
    const int n0 = blockIdx.x * 128, m0 = blockIdx.y * 128;   // n fastest

    float acc[2][8][4] = {};
    const int nch = K >> 5;

    auto issue = [&](int kc, int st) {
        uint32_t sb = sbase + (uint32_t)st * 40960u;
        #pragma unroll
        for (int i = t; i < 1024; i += 256) {     // A: planes h,l (128 rows x 32 bf16)
            int p = i >> 9, e = i & 511, r = e >> 2, q = e & 3;
            int row = m0 + r; if (row >= M) row = M - 1;   // clamp; rows >= M never written
            cp16(sb + (uint32_t)(p * 10240 + (r * SAS + q * 4) * 4),
                 (p ? Al : Ah) + (size_t)row * lda + kc * 32 + q * 8);
        }
        #pragma unroll
        for (int i = t; i < 1024; i += 256) {     // B: planes h,l
            int p = i >> 9, e = i & 511, r = e >> 2, q = e & 3;
            cp16(sb + (uint32_t)(20480 + p * 10240 + (r * SAS + q * 4) * 4),
                 (p ? Bl : Bh) + (size_t)(n0 + r) * K + kc * 32 + q * 8);
        }
    };

    issue(0, 0); CP_COMMIT();

    const int aRowL = lane & 15;
    const uint32_t aOffB = (uint32_t)((lane >> 4) << 4);
    const int bRowL = (lane & 7) + ((lane >> 4) << 3);
    const uint32_t bOffB = (uint32_t)(((lane >> 3) & 1) << 4);

    for (int kc = 0; kc < nch; kc++) {
        int st = kc & 1;
        if (kc + 1 < nch) { issue(kc + 1, st ^ 1); CP_COMMIT(); CP_WAIT(1); }
        else              { CP_WAIT(0); }
        __syncthreads();

        uint32_t stb = sbase + (uint32_t)st * 40960u;
        #pragma unroll
        for (int s = 0; s < 2; s++) {
            uint32_t ah[2][4], al[2][4];
            #pragma unroll
            for (int mf = 0; mf < 2; mf++) {
                uint32_t ra = (uint32_t)(((wm * 32 + mf * 16 + aRowL) * SAS + s * 8) * 4) + aOffB;
                ldsm4(ah[mf][0], ah[mf][1], ah[mf][2], ah[mf][3], stb + ra);
                ldsm4(al[mf][0], al[mf][1], al[mf][2], al[mf][3], stb + 10240 + ra);
            }
            #pragma unroll
            for (int nfp = 0; nfp < 4; nfp++) {
                uint32_t rb = (uint32_t)(((wn * 64 + nfp * 16 + bRowL) * SAS + s * 8) * 4) + bOffB;
                uint32_t bh[4], bl[4];
                ldsm4(bh[0], bh[1], bh[2], bh[3], stb + 20480 + rb);
                ldsm4(bl[0], bl[1], bl[2], bl[3], stb + 30720 + rb);
                #pragma unroll
                for (int mf = 0; mf < 2; mf++) {
                    mma16816(acc[mf][2 * nfp],     ah[mf], bh[0], bh[1]);
                    mma16816(acc[mf][2 * nfp],     ah[mf], bl[0], bl[1]);
                    mma16816(acc[mf][2 * nfp],     al[mf], bh[0], bh[1]);
                    mma16816(acc[mf][2 * nfp + 1], ah[mf], bh[2], bh[3]);
                    mma16816(acc[mf][2 * nfp + 1], ah[mf], bl[2], bl[3]);
                    mma16816(acc[mf][2 * nfp + 1], al[mf], bh[2], bh[3]);
                }
            }
        }
        __syncthreads();
    }

    // ---- epilogue ----
    #pragma unroll
    for (int mf = 0; mf < 2; mf++) {
        int r0 = m0 + wm * 32 + mf * 16 + lr;
        int r1 = r0 + 8;
        #pragma unroll
        for (int nf = 0; nf < 8; nf++) {
            int col = n0 + wn * 64 + nf * 8 + 2 * lc;
            float c0 = acc[mf][nf][0], c1 = acc[mf][nf][1];
            float c2 = acc[mf][nf][2], c3 = acc[mf][nf][3];
            if (MODE == 0) {
                if (r0 < M) *reinterpret_cast<float2*>(C + (size_t)r0 * ldc + col) = make_float2(c0, c1);
                if (r1 < M) *reinterpret_cast<float2*>(C + (size_t)r1 * ldc + col) = make_float2(c2, c3);
            } else if (MODE == 1) {
                __half* Ch = reinterpret_cast<__half*>(C);
                if (r0 < M) *reinterpret_cast<__half2*>(Ch + (size_t)r0 * ldc + col) =
                    __floats2half2_rn(sigm(c0), sigm(c1));
                if (r1 < M) *reinterpret_cast<__half2*>(Ch + (size_t)r1 * ldc + col) =
                    __floats2half2_rn(sigm(c2), sigm(c3));
            } else {
                int j = col >> 1;
                float bgj = bgp[j], bvj = bvp[j];
                if (r0 < M) {
                    float cg = 0.f, cv = 0.f;
                    if (Cc) { float2 cc = *reinterpret_cast<const float2*>(Cc + (size_t)(r0 >> 4) * 512 + col); cg = cc.x; cv = cc.y; }
                    float h = gelu_tanh(c0 + cg + bgj) * (c1 + cv + bvj);
                    split_bf16(h, Oh[(size_t)r0 * 256 + j], Ol[(size_t)r0 * 256 + j]);
                }
                if (r1 < M) {
                    float cg = 0.f, cv = 0.f;
                    if (Cc) { float2 cc = *reinterpret_cast<const float2*>(Cc + (size_t)(r1 >> 4) * 512 + col); cg = cc.x; cv = cc.y; }
                    float h = gelu_tanh(c2 + cg + bgj) * (c3 + cv + bvj);
                    split_bf16(h, Oh[(size_t)r1 * 256 + j], Ol[(size_t)r1 * 256 + j]);
                }
            }
        }
    }
}

// ======================= elementwise / prep kernels =======================
__global__ void zero_out_kernel() {
    int i = blockIdx.x * blockDim.x + threadIdx.x;
    if (i < NNODES * DDIM) g_outg[i] = 0.0f;
}

__global__ void prep_weights_kernel(
    const float* __restrict__ Wg1, const float* __restrict__ Wv1,
    const float* __restrict__ Wo1, const float* __restrict__ Win,
    const float* __restrict__ Wou, const float* __restrict__ Wg2,
    const float* __restrict__ Wv2, const float* __restrict__ Wo2)
{
    int i = blockIdx.x * blockDim.x + threadIdx.x;
    int stride = gridDim.x * blockDim.x;
    for (int x = i; x < 512 * 256; x += stride) {   // W13i
        int n = x >> 8, k = x & 255;
        int j = n >> 1;
        const float* W = (n & 1) ? Wv1 : Wg1;
        int krow = (k < 128) ? k : (256 + (k - 128));
        split_bf16(W[krow * 256 + j], gW13h[x], gW13l[x]);
    }
    for (int x = i; x < 512 * 128; x += stride) {   // Wceni
        int n = x >> 7, k = x & 127;
        int j = n >> 1;
        const float* W = (n & 1) ? Wv1 : Wg1;
        split_bf16(W[(128 + k) * 256 + j], gWch[x], gWcl[x]);
    }
    for (int x = i; x < 128 * 256; x += stride) {   // Bo1
        int n = x >> 8, k = x & 255;
        split_bf16(Wo1[k * 128 + n], gBo1h[x], gBo1l[x]);
    }
    for (int x = i; x < 256 * 128; x += stride) {   // Bio
        int n = x >> 7, k = x & 127;
        const float* W = (n < 128) ? Win : Wou;
        split_bf16(W[k * 128 + (n & 127)], gBioh[x], gBiol[x]);
    }
    for (int x = i; x < 512 * 384; x += stride) {   // B2i
        int n = x / 384, k = x % 384;
        int j = n >> 1;
        const float* W = (n & 1) ? Wv2 : Wg2;
        split_bf16(W[k * 256 + j], gB2h[x], gB2l[x]);
    }
    for (int x = i; x < 128 * 256; x += stride) {   // Bo2
        int n = x >> 8, k = x & 255;
        split_bf16(Wo2[k * 128 + n], gBo2h[x], gBo2l[x]);
    }
}

__global__ void prep_A1_kernel(const float* __restrict__ pair, const float* __restrict__ local,
                               const int* __restrict__ nbrs)
{
    size_t i = (size_t)blockIdx.x * blockDim.x + threadIdx.x;
    if (i >= (size_t)NR * 256) return;
    int c = (int)(i & 255);
    size_t r = i >> 8;
    float v;
    if (c < 128) {
        v = pair[r * 128 + c];
    } else {
        int nb = nbrs[r];
        if (nb < 0) nb += NNODES;   // python wrap for -1
        v = local[(size_t)nb * 128 + (c - 128)];
    }
    split_bf16(v, g_A1h[i], g_A1l[i]);
}

__global__ void prep_L_kernel(const float* __restrict__ local) {
    int i = blockIdx.x * blockDim.x + threadIdx.x;
    if (i < NNODES * DDIM) split_bf16(local[i], g_Lh[i], g_Ll[i]);
}

__global__ void ln_pair_kernel(const float* __restrict__ pair, const float* __restrict__ bo,
                               const float* __restrict__ gp, const float* __restrict__ bp,
                               float* __restrict__ out)
{
    int row = blockIdx.x * 8 + (threadIdx.x >> 5);
    int lane = threadIdx.x & 31;
    if (row >= NR) return;
    const float* up = g_upre + (size_t)row * 128;
    float v[4], s = 0.0f, sq = 0.0f;
    #pragma unroll
    for (int j = 0; j < 4; j++) {
        int col = lane + j * 32;
        v[j] = up[col] + bo[col];
        s += v[j]; sq += v[j] * v[j];
    }
    #pragma unroll
    for (int o = 16; o > 0; o >>= 1) {
        s  += __shfl_xor_sync(0xffffffffu, s, o);
        sq += __shfl_xor_sync(0xffffffffu, sq, o);
    }
    float m = s * (1.0f / 128.0f);
    float var = sq * (1.0f / 128.0f) - m * m;
    float rstd = rsqrtf(var + 1e-5f);
    #pragma unroll
    for (int j = 0; j < 4; j++) {
        int col = lane + j * 32;
        float pu = (v[j] - m) * rstd * gp[col] + bp[col];
        g_pu[(size_t)row * 128 + col] = pu;
        out[(size_t)NNODES * 128 + (size_t)row * 128 + col] = pair[(size_t)row * 128 + col] + pu;
    }
}

__global__ void messages_kernel(const int* __restrict__ nbrs, const float* __restrict__ mask) {
    int n = blockIdx.x;
    int c = threadIdx.x;   // 128 threads
    float inc = 0.0f;
    #pragma unroll
    for (int kk = 0; kk < KNBR; kk++) {
        int row = n * KNBR + kk;
        int nb = nbrs[row];
        int nbw = (nb < 0) ? nb + NNODES : nb;
        bool valid = (nb != -1) && (mask[nbw] > 0.0f);
        if (valid) {
            float p  = g_pu[(size_t)row * 128 + c];
            float si = __half2float(g_S[(size_t)row * 256 + c]);
            float so = __half2float(g_S[(size_t)row * 256 + 128 + c]);
            inc += si * p;
            atomicAdd(&g_outg[nbw * 128 + c], so * p);
        }
    }
    g_inc[n * 128 + c] = inc;
}

__global__ void prep_X2_kernel(const float* __restrict__ local) {
    int i = blockIdx.x * blockDim.x + threadIdx.x;
    if (i >= NNODES * 384) return;
    int k = i % 384;
    int r = i / 384;
    float v;
    if (k < 128)       v = local[(size_t)r * 128 + k];
    else if (k < 256)  v = g_inc[r * 128 + (k - 128)];
    else               v = g_outg[r * 128 + (k - 256)];
    split_bf16(v, g_X2h[i], g_X2l[i]);
}

__global__ void ln_local_kernel(const float* __restrict__ local, const float* __restrict__ bo,
                                const float* __restrict__ gl, const float* __restrict__ bl,
                                float* __restrict__ out)
{
    int row = blockIdx.x * 8 + (threadIdx.x >> 5);
    int lane = threadIdx.x & 31;
    if (row >= NNODES) return;
    const float* up = g_upre + (size_t)row * 128;
    float v[4], s = 0.0f, sq = 0.0f;
    #pragma unroll
    for (int j = 0; j < 4; j++) {
        int col = lane + j * 32;
        v[j] = up[col] + bo[col];
        s += v[j]; sq += v[j] * v[j];
    }
    #pragma unroll
    for (int o = 16; o > 0; o >>= 1) {
        s  += __shfl_xor_sync(0xffffffffu, s, o);
        sq += __shfl_xor_sync(0xffffffffu, sq, o);
    }
    float m = s * (1.0f / 128.0f);
    float var = sq * (1.0f / 128.0f) - m * m;
    float rstd = rsqrtf(var + 1e-5f);
    #pragma unroll
    for (int j = 0; j < 4; j++) {
        int col = lane + j * 32;
        float lu = (v[j] - m) * rstd * gl[col] + bl[col];
        out[(size_t)row * 128 + col] = local[(size_t)row * 128 + col] + lu;
    }
}

// ======================= launch =======================
extern "C" void kernel_launch(void* const* d_in, const int* in_sizes, int n_in,
                              void* d_out, int out_size)
{
    const float* local = (const float*)d_in[0];
    const float* pair  = (const float*)d_in[1];
    const int*   nbrs  = (const int*)  d_in[2];
    const float* mask  = (const float*)d_in[3];
    const float* Wg1 = (const float*)d_in[4];
    const float* bg1 = (const float*)d_in[5];
    const float* Wv1 = (const float*)d_in[6];
    const float* bv1 = (const float*)d_in[7];
    const float* Wo1 = (const float*)d_in[8];
    const float* bo1 = (const float*)d_in[9];
    const float* gp  = (const float*)d_in[10];
    const float* bp  = (const float*)d_in[11];
    const float* Win = (const float*)d_in[12];
    const float* Wou = (const float*)d_in[13];
    const float* Wg2 = (const float*)d_in[14];
    const float* bg2 = (const float*)d_in[15];
    const float* Wv2 = (const float*)d_in[16];
    const float* bv2 = (const float*)d_in[17];
    const float* Wo2 = (const float*)d_in[18];
    const float* bo2 = (const float*)d_in[19];
    const float* gl  = (const float*)d_in[20];
    const float* bl  = (const float*)d_in[21];
    float* out = (float*)d_out;

    cudaFuncSetAttribute(gemm_kernel<0>, cudaFuncAttributeMaxDynamicSharedMemorySize, DSMEM);
    cudaFuncSetAttribute(gemm_kernel<1>, cudaFuncAttributeMaxDynamicSharedMemorySize, DSMEM);
    cudaFuncSetAttribute(gemm_kernel<2>, cudaFuncAttributeMaxDynamicSharedMemorySize, DSMEM);

    float *gupre, *gcc;
    cudaGetSymbolAddress((void**)&gupre, g_upre);
    cudaGetSymbolAddress((void**)&gcc,   g_Cc);
    __half* gsh;
    cudaGetSymbolAddress((void**)&gsh, g_S);
    __nv_bfloat16 *a1h, *a1l, *hh, *hl, *lh, *ll, *x2h, *x2l, *x3h, *x3l;
    cudaGetSymbolAddress((void**)&a1h, g_A1h); cudaGetSymbolAddress((void**)&a1l, g_A1l);
    cudaGetSymbolAddress((void**)&hh,  g_Hh);  cudaGetSymbolAddress((void**)&hl,  g_Hl);
    cudaGetSymbolAddress((void**)&lh,  g_Lh);  cudaGetSymbolAddress((void**)&ll,  g_Ll);
    cudaGetSymbolAddress((void**)&x2h, g_X2h); cudaGetSymbolAddress((void**)&x2l, g_X2l);
    cudaGetSymbolAddress((void**)&x3h, g_X3h); cudaGetSymbolAddress((void**)&x3l, g_X3l);
    __nv_bfloat16 *w13h, *w13l, *wch, *wcl, *bo1h, *bo1l, *bioh, *biol, *b2h, *b2l, *bo2h, *bo2l;
    cudaGetSymbolAddress((void**)&w13h, gW13h); cudaGetSymbolAddress((void**)&w13l, gW13l);
    cudaGetSymbolAddress((void**)&wch,  gWch);  cudaGetSymbolAddress((void**)&wcl,  gWcl);
    cudaGetSymbolAddress((void**)&bo1h, gBo1h); cudaGetSymbolAddress((void**)&bo1l, gBo1l);
    cudaGetSymbolAddress((void**)&bioh, gBioh); cudaGetSymbolAddress((void**)&biol, gBiol);
    cudaGetSymbolAddress((void**)&b2h,  gB2h);  cudaGetSymbolAddress((void**)&b2l,  gB2l);
    cudaGetSymbolAddress((void**)&bo2h, gBo2h); cudaGetSymbolAddress((void**)&bo2l, gBo2l);

    // 1) prep
    zero_out_kernel<<<(NNODES * DDIM + 255) / 256, 256>>>();
    prep_weights_kernel<<<512, 256>>>(Wg1, Wv1, Wo1, Win, Wou, Wg2, Wv2, Wo2);
    prep_A1_kernel<<<(int)(((size_t)NR * 256 + 255) / 256), 256>>>(pair, local, nbrs);
    prep_L_kernel<<<(NNODES * DDIM + 255) / 256, 256>>>(local);

    // 2) Cc = local @ Wceni : [20000,128]x[128,512]
    gemm_kernel<0><<<dim3(4, 157), 256, DSMEM>>>(lh, ll, 128, NNODES, 128, wch, wcl,
                                                 gcc, 512, nullptr, nullptr, nullptr, nullptr, nullptr);
    // 3) H = gelu(A1@W13i + Cc + bg) * (… + bv) -> split bf16 Hh/Hl
    gemm_kernel<2><<<dim3(4, 2500), 256, DSMEM>>>(a1h, a1l, 256, NR, 256, w13h, w13l,
                                                  nullptr, 0, gcc, bg1, bv1, hh, hl);
    // 4) u_pre = H @ Bo1 : [320000,256]x[256,128] -> g_upre
    gemm_kernel<0><<<dim3(1, 2500), 256, DSMEM>>>(hh, hl, 256, NR, 256, bo1h, bo1l,
                                                  gupre, 128, nullptr, nullptr, nullptr, nullptr, nullptr);
    // 5) gates S = sigmoid(A1.pair @ [Win||Wou]) -> fp16 g_S
    gemm_kernel<1><<<dim3(2, 2500), 256, DSMEM>>>(a1h, a1l, 256, NR, 128, bioh, biol,
                                                  (float*)gsh, 256, nullptr, nullptr, nullptr, nullptr, nullptr);
    // 6) LN pair + residual pair output + store pu (adds bo1 inline, as R13)
    ln_pair_kernel<<<(NR + 7) / 8, 256>>>(pair, bo1, gp, bp, out);
    // 7) incoming sum + outgoing atomic scatter (fp16 gate reads)
    messages_kernel<<<NNODES, 128>>>(nbrs, mask);
    // 8) local features
    prep_X2_kernel<<<(NNODES * 384 + 255) / 256, 256>>>(local);
    // 9) X3 = fused local MLP hidden : [20000,384]x[384,512]
    gemm_kernel<2><<<dim3(4, 157), 256, DSMEM>>>(x2h, x2l, 384, NNODES, 384, b2h, b2l,
                                                 nullptr, 0, nullptr, bg2, bv2, x3h, x3l);
    // 10) u2_pre = X3 @ Bo2 -> g_upre (reuse)
    gemm_kernel<0><<<dim3(1, 157), 256, DSMEM>>>(x3h, x3l, 256, NNODES, 256, bo2h, bo2l,
                                                 gupre, 128, nullptr, nullptr, nullptr, nullptr, nullptr);
    // 11) LN local + residual local output
    ln_local_kernel<<<(NNODES + 7) / 8, 256>>>(local, bo2, gl, bl, out);
}

// round 17
// speedup vs baseline: 1.1100x; 1.0062x over previous
#include <cuda_runtime.h>
#include <cuda_bf16.h>
#include <cuda_fp16.h>
#include <cstdint>
#include <math.h>

#define NNODES 20000
#define KNBR 16
#define DDIM 128
#define NR (NNODES * KNBR)   /* 320000 pair rows */
#define SAS 20               /* padded smem row stride in uint32 */
#define DSMEM 81920          /* 2 stages x 4 planes x 128 x SAS x 4B */

// ======================= device scratch (allocation-free) =======================
__device__ __nv_bfloat16 g_A1h[(size_t)NR * 256];
__device__ __nv_bfloat16 g_A1l[(size_t)NR * 256];
__device__ __half        g_S[(size_t)NR * 256];       // fp16 sigmoid gates (si | so)
__device__ float         g_upre[(size_t)NR * 128];    // u pre-LN (pair); reused by local tail
__device__ float         g_pu[(size_t)NR * 128];
__device__ __nv_bfloat16 g_Hh[(size_t)NR * 256];
__device__ __nv_bfloat16 g_Hl[(size_t)NR * 256];
__device__ float         g_Cc[(size_t)NNODES * 512];  // interleaved (g,v) per node
__device__ float         g_inc[NNODES * DDIM];
__device__ float         g_outg[NNODES * DDIM];
__device__ __nv_bfloat16 g_Lh[NNODES * DDIM], g_Ll[NNODES * DDIM];
__device__ __nv_bfloat16 g_X2h[NNODES * 384], g_X2l[NNODES * 384];
__device__ __nv_bfloat16 g_X3h[(size_t)NNODES * 256], g_X3l[(size_t)NNODES * 256];
// weights, split bf16, stored [n][k] (K-major rows); MLP hidden weights INTERLEAVED: n=2j+s (s=0 gate, 1 value)
__device__ __nv_bfloat16 gW13h[512 * 256], gW13l[512 * 256];
__device__ __nv_bfloat16 gWch[512 * 128],  gWcl[512 * 128];
__device__ __nv_bfloat16 gBo1h[128 * 256], gBo1l[128 * 256];
__device__ __nv_bfloat16 gBioh[256 * 128], gBiol[256 * 128];
__device__ __nv_bfloat16 gB2h[512 * 384],  gB2l[512 * 384];
__device__ __nv_bfloat16 gBo2h[128 * 256], gBo2l[128 * 256];

// ======================= helpers =======================
__device__ __forceinline__ uint32_t smem_to_u32(const void* p) {
    uint32_t a;
    asm("{ .reg .u64 t; cvta.to.shared.u64 t, %1; cvt.u32.u64 %0, t; }" : "=r"(a) : "l"(p));
    return a;
}
__device__ __forceinline__ float gelu_tanh(float x) {
    float x3 = x * x * x;
    return 0.5f * x * (1.0f + tanhf(0.7978845608028654f * (x + 0.044715f * x3)));
}
__device__ __forceinline__ float sigm(float x) { return 1.0f / (1.0f + expf(-x)); }
__device__ __forceinline__ void split_bf16(float v, __nv_bfloat16& h, __nv_bfloat16& l) {
    h = __float2bfloat16(v);
    l = __float2bfloat16(v - __bfloat162float(h));
}
__device__ __forceinline__ void mma16816(float* c, const uint32_t* a, uint32_t b0, uint32_t b1) {
    asm volatile(
        "mma.sync.aligned.m16n8k16.row.col.f32.bf16.bf16.f32 "
        "{%0,%1,%2,%3}, {%4,%5,%6,%7}, {%8,%9}, {%0,%1,%2,%3};"
        : "+f"(c[0]), "+f"(c[1]), "+f"(c[2]), "+f"(c[3])
        : "r"(a[0]), "r"(a[1]), "r"(a[2]), "r"(a[3]), "r"(b0), "r"(b1));
}
__device__ __forceinline__ void ldsm4(uint32_t& r0, uint32_t& r1, uint32_t& r2, uint32_t& r3, uint32_t addr) {
    asm volatile("ldmatrix.sync.aligned.m8n8.x4.shared.b16 {%0,%1,%2,%3}, [%4];"
                 : "=r"(r0), "=r"(r1), "=r"(r2), "=r"(r3) : "r"(addr));
}
__device__ __forceinline__ void cp16(uint32_t dst, const void* src) {
    asm volatile("cp.async.cg.shared.global [%0], [%1], 16;" :: "r"(dst), "l"(src));
}
#define CP_COMMIT() asm volatile("cp.async.commit_group;" ::: "memory")
#define CP_WAIT(n)  asm volatile("cp.async.wait_group %0;" :: "n"(n) : "memory")

// ======================= split-bf16 GEMM (mma.sync + ldmatrix + cp.async) ==========
// C[m0:+128, n0:+128] = (Ah+Al)[M,K] @ (Bh+Bl)[N,K]^T; 3-term split AhBh+AhBl+AlBh.
// MODE 0: fp32 out.  MODE 1: sigmoid -> fp16 out (C as __half*, ldc in half units).
// MODE 2: fused gated-MLP epilogue (interleaved g|v cols -> split bf16 Oh/Ol, 256-wide).
// Grid: n fastest (blockIdx.x = n-block) -> consecutive CTAs share the A tile in L2.
// __launch_bounds__(256, 2): cap regs at 128/thread so 2 CTAs/SM are resident.
template <int MODE>
__global__ void __launch_bounds__(256, 2)
gemm_kernel(const __nv_bfloat16* __restrict__ Ah, const __nv_bfloat16* __restrict__ Al,
            int lda, int M, int K,
            const __nv_bfloat16* __restrict__ Bh, const __nv_bfloat16* __restrict__ Bl,
            float* __restrict__ C, int ldc,
            const float* __restrict__ Cc,
            const float* __restrict__ bgp, const float* __restrict__ bvp,
            __nv_bfloat16* __restrict__ Oh, __nv_bfloat16* __restrict__ Ol)
{
    extern __shared__ __align__(16) uint32_t dynsmem[];
    const uint32_t sbase = smem_to_u32(dynsmem);
    const int t = threadIdx.x, wid = t >> 5, lane = t & 31;
    const int lr = lane >> 2, lc = lane & 3;
    const int wm = wid & 3, wn = wid >> 2;
    const int n0 = blockIdx.x * 128, m0 = blockIdx.y * 128;   // n fastest

    float acc[2][8][4] = {};
    const int nch = K >> 5;

    auto issue = [&](int kc, int st) {
        uint32_t sb = sbase + (uint32_t)st * 40960u;
        #pragma unroll
        for (int i = t; i < 1024; i += 256) {     // A: planes h,l (128 rows x 32 bf16)
            int p = i >> 9, e = i & 511, r = e >> 2, q = e & 3;
            int row = m0 + r; if (row >= M) row = M - 1;   // clamp; rows >= M never written
            cp16(sb + (uint32_t)(p * 10240 + (r * SAS + q * 4) * 4),
                 (p ? Al : Ah) + (size_t)row * lda + kc * 32 + q * 8);
        }
        #pragma unroll
        for (int i = t; i < 1024; i += 256) {     // B: planes h,l
            int p = i >> 9, e = i & 511, r = e >> 2, q = e & 3;
            cp16(sb + (uint32_t)(20480 + p * 10240 + (r * SAS + q * 4) * 4),
                 (p ? Bl : Bh) + (size_t)(n0 + r) * K + kc * 32 + q * 8);
        }
    };

    issue(0, 0); CP_COMMIT();

    const int aRowL = lane & 15;
    const uint32_t aOffB = (uint32_t)((lane >> 4) << 4);
    const int bRowL = (lane & 7) + ((lane >> 4) << 3);
    const uint32_t bOffB = (uint32_t)(((lane >> 3) & 1) << 4);

    for (int kc = 0; kc < nch; kc++) {
        int st = kc & 1;
        if (kc + 1 < nch) { issue(kc + 1, st ^ 1); CP_COMMIT(); CP_WAIT(1); }
        else              { CP_WAIT(0); }
        __syncthreads();

        uint32_t stb = sbase + (uint32_t)st * 40960u;
        #pragma unroll
        for (int s = 0; s < 2; s++) {
            uint32_t ah[2][4], al[2][4];
            #pragma unroll
            for (int mf = 0; mf < 2; mf++) {
                uint32_t ra = (uint32_t)(((wm * 32 + mf * 16 + aRowL) * SAS + s * 8) * 4) + aOffB;
                ldsm4(ah[mf][0], ah[mf][1], ah[mf][2], ah[mf][3], stb + ra);
                ldsm4(al[mf][0], al[mf][1], al[mf][2], al[mf][3], stb + 10240 + ra);
            }
            #pragma unroll
            for (int nfp = 0; nfp < 4; nfp++) {
                uint32_t rb = (uint32_t)(((wn * 64 + nfp * 16 + bRowL) * SAS + s * 8) * 4) + bOffB;
                uint32_t bh[4], bl[4];
                ldsm4(bh[0], bh[1], bh[2], bh[3], stb + 20480 + rb);
                ldsm4(bl[0], bl[1], bl[2], bl[3], stb + 30720 + rb);
                #pragma unroll
                for (int mf = 0; mf < 2; mf++) {
                    mma16816(acc[mf][2 * nfp],     ah[mf], bh[0], bh[1]);
                    mma16816(acc[mf][2 * nfp],     ah[mf], bl[0], bl[1]);
                    mma16816(acc[mf][2 * nfp],     al[mf], bh[0], bh[1]);
                    mma16816(acc[mf][2 * nfp + 1], ah[mf], bh[2], bh[3]);
                    mma16816(acc[mf][2 * nfp + 1], ah[mf], bl[2], bl[3]);
                    mma16816(acc[mf][2 * nfp + 1], al[mf], bh[2], bh[3]);
                }
            }
        }
        __syncthreads();
    }

    // ---- epilogue ----
    #pragma unroll
    for (int mf = 0; mf < 2; mf++) {
        int r0 = m0 + wm * 32 + mf * 16 + lr;
        int r1 = r0 + 8;
        #pragma unroll
        for (int nf = 0; nf < 8; nf++) {
            int col = n0 + wn * 64 + nf * 8 + 2 * lc;
            float c0 = acc[mf][nf][0], c1 = acc[mf][nf][1];
            float c2 = acc[mf][nf][2], c3 = acc[mf][nf][3];
            if (MODE == 0) {
                if (r0 < M) *reinterpret_cast<float2*>(C + (size_t)r0 * ldc + col) = make_float2(c0, c1);
                if (r1 < M) *reinterpret_cast<float2*>(C + (size_t)r1 * ldc + col) = make_float2(c2, c3);
            } else if (MODE == 1) {
                __half* Ch = reinterpret_cast<__half*>(C);
                if (r0 < M) *reinterpret_cast<__half2*>(Ch + (size_t)r0 * ldc + col) =
                    __floats2half2_rn(sigm(c0), sigm(c1));
                if (r1 < M) *reinterpret_cast<__half2*>(Ch + (size_t)r1 * ldc + col) =
                    __floats2half2_rn(sigm(c2), sigm(c3));
            } else {
                int j = col >> 1;
                float bgj = bgp[j], bvj = bvp[j];
                if (r0 < M) {
                    float cg = 0.f, cv = 0.f;
                    if (Cc) { float2 cc = *reinterpret_cast<const float2*>(Cc + (size_t)(r0 >> 4) * 512 + col); cg = cc.x; cv = cc.y; }
                    float h = gelu_tanh(c0 + cg + bgj) * (c1 + cv + bvj);
                    split_bf16(h, Oh[(size_t)r0 * 256 + j], Ol[(size_t)r0 * 256 + j]);
                }
                if (r1 < M) {
                    float cg = 0.f, cv = 0.f;
                    if (Cc) { float2 cc = *reinterpret_cast<const float2*>(Cc + (size_t)(r1 >> 4) * 512 + col); cg = cc.x; cv = cc.y; }
                    float h = gelu_tanh(c2 + cg + bgj) * (c3 + cv + bvj);
                    split_bf16(h, Oh[(size_t)r1 * 256 + j], Ol[(size_t)r1 * 256 + j]);
                }
            }
        }
    }
}

// ======================= elementwise / prep kernels =======================
__global__ void zero_out_kernel() {
    int i = blockIdx.x * blockDim.x + threadIdx.x;
    if (i < NNODES * DDIM) g_outg[i] = 0.0f;
}

__global__ void prep_weights_kernel(
    const float* __restrict__ Wg1, const float* __restrict__ Wv1,
    const float* __restrict__ Wo1, const float* __restrict__ Win,
    const float* __restrict__ Wou, const float* __restrict__ Wg2,
    const float* __restrict__ Wv2, const float* __restrict__ Wo2)
{
    int i = blockIdx.x * blockDim.x + threadIdx.x;
    int stride = gridDim.x * blockDim.x;
    for (int x = i; x < 512 * 256; x += stride) {   // W13i
        int n = x >> 8, k = x & 255;
        int j = n >> 1;
        const float* W = (n & 1) ? Wv1 : Wg1;
        int krow = (k < 128) ? k : (256 + (k - 128));
        split_bf16(W[krow * 256 + j], gW13h[x], gW13l[x]);
    }
    for (int x = i; x < 512 * 128; x += stride) {   // Wceni
        int n = x >> 7, k = x & 127;
        int j = n >> 1;
        const float* W = (n & 1) ? Wv1 : Wg1;
        split_bf16(W[(128 + k) * 256 + j], gWch[x], gWcl[x]);
    }
    for (int x = i; x < 128 * 256; x += stride) {   // Bo1
        int n = x >> 8, k = x & 255;
        split_bf16(Wo1[k * 128 + n], gBo1h[x], gBo1l[x]);
    }
    for (int x = i; x < 256 * 128; x += stride) {   // Bio
        int n = x >> 7, k = x & 127;
        const float* W = (n < 128) ? Win : Wou;
        split_bf16(W[k * 128 + (n & 127)], gBioh[x], gBiol[x]);
    }
    for (int x = i; x < 512 * 384; x += stride) {   // B2i
        int n = x / 384, k = x % 384;
        int j = n >> 1;
        const float* W = (n & 1) ? Wv2 : Wg2;
        split_bf16(W[k * 256 + j], gB2h[x], gB2l[x]);
    }
    for (int x = i; x < 128 * 256; x += stride) {   // Bo2
        int n = x >> 8, k = x & 255;
        split_bf16(Wo2[k * 128 + n], gBo2h[x], gBo2l[x]);
    }
}

__global__ void prep_A1_kernel(const float* __restrict__ pair, const float* __restrict__ local,
                               const int* __restrict__ nbrs)
{
    size_t i = (size_t)blockIdx.x * blockDim.x + threadIdx.x;
    if (i >= (size_t)NR * 256) return;
    int c = (int)(i & 255);
    size_t r = i >> 8;
    float v;
    if (c < 128) {
        v = pair[r * 128 + c];
    } else {
        int nb = nbrs[r];
        if (nb < 0) nb += NNODES;   // python wrap for -1
        v = local[(size_t)nb * 128 + (c - 128)];
    }
    split_bf16(v, g_A1h[i], g_A1l[i]);
}

__global__ void prep_L_kernel(const float* __restrict__ local) {
    int i = blockIdx.x * blockDim.x + threadIdx.x;
    if (i < NNODES * DDIM) split_bf16(local[i], g_Lh[i], g_Ll[i]);
}

__global__ void ln_pair_kernel(const float* __restrict__ pair, const float* __restrict__ bo,
                               const float* __restrict__ gp, const float* __restrict__ bp,
                               float* __restrict__ out)
{
    int row = blockIdx.x * 8 + (threadIdx.x >> 5);
    int lane = threadIdx.x & 31;
    if (row >= NR) return;
    const float* up = g_upre + (size_t)row * 128;
    float v[4], s = 0.0f, sq = 0.0f;
    #pragma unroll
    for (int j = 0; j < 4; j++) {
        int col = lane + j * 32;
        v[j] = up[col] + bo[col];
        s += v[j]; sq += v[j] * v[j];
    }
    #pragma unroll
    for (int o = 16; o > 0; o >>= 1) {
        s  += __shfl_xor_sync(0xffffffffu, s, o);
        sq += __shfl_xor_sync(0xffffffffu, sq, o);
    }
    float m = s * (1.0f / 128.0f);
    float var = sq * (1.0f / 128.0f) - m * m;
    float rstd = rsqrtf(var + 1e-5f);
    #pragma unroll
    for (int j = 0; j < 4; j++) {
        int col = lane + j * 32;
        float pu = (v[j] - m) * rstd * gp[col] + bp[col];
        g_pu[(size_t)row * 128 + col] = pu;
        out[(size_t)NNODES * 128 + (size_t)row * 128 + col] = pair[(size_t)row * 128 + col] + pu;
    }
}

__global__ void messages_kernel(const int* __restrict__ nbrs, const float* __restrict__ mask) {
    int n = blockIdx.x;
    int c = threadIdx.x;   // 128 threads
    float inc = 0.0f;
    #pragma unroll
    for (int kk = 0; kk < KNBR; kk++) {
        int row = n * KNBR + kk;
        int nb = nbrs[row];
        int nbw = (nb < 0) ? nb + NNODES : nb;
        bool valid = (nb != -1) && (mask[nbw] > 0.0f);
        if (valid) {
            float p  = g_pu[(size_t)row * 128 + c];
            float si = __half2float(g_S[(size_t)row * 256 + c]);
            float so = __half2float(g_S[(size_t)row * 256 + 128 + c]);
            inc += si * p;
            atomicAdd(&g_outg[nbw * 128 + c], so * p);
        }
    }
    g_inc[n * 128 + c] = inc;
}

__global__ void prep_X2_kernel(const float* __restrict__ local) {
    int i = blockIdx.x * blockDim.x + threadIdx.x;
    if (i >= NNODES * 384) return;
    int k = i % 384;
    int r = i / 384;
    float v;
    if (k < 128)       v = local[(size_t)r * 128 + k];
    else if (k < 256)  v = g_inc[r * 128 + (k - 128)];
    else               v = g_outg[r * 128 + (k - 256)];
    split_bf16(v, g_X2h[i], g_X2l[i]);
}

__global__ void ln_local_kernel(const float* __restrict__ local, const float* __restrict__ bo,
                                const float* __restrict__ gl, const float* __restrict__ bl,
                                float* __restrict__ out)
{
    int row = blockIdx.x * 8 + (threadIdx.x >> 5);
    int lane = threadIdx.x & 31;
    if (row >= NNODES) return;
    const float* up = g_upre + (size_t)row * 128;
    float v[4], s = 0.0f, sq = 0.0f;
    #pragma unroll
    for (int j = 0; j < 4; j++) {
        int col = lane + j * 32;
        v[j] = up[col] + bo[col];
        s += v[j]; sq += v[j] * v[j];
    }
    #pragma unroll
    for (int o = 16; o > 0; o >>= 1) {
        s  += __shfl_xor_sync(0xffffffffu, s, o);
        sq += __shfl_xor_sync(0xffffffffu, sq, o);
    }
    float m = s * (1.0f / 128.0f);
    float var = sq * (1.0f / 128.0f) - m * m;
    float rstd = rsqrtf(var + 1e-5f);
    #pragma unroll
    for (int j = 0; j < 4; j++) {
        int col = lane + j * 32;
        float lu = (v[j] - m) * rstd * gl[col] + bl[col];
        out[(size_t)row * 128 + col] = local[(size_t)row * 128 + col] + lu;
    }
}

// ======================= launch =======================
extern "C" void kernel_launch(void* const* d_in, const int* in_sizes, int n_in,
                              void* d_out, int out_size)
{
    const float* local = (const float*)d_in[0];
    const float* pair  = (const float*)d_in[1];
    const int*   nbrs  = (const int*)  d_in[2];
    const float* mask  = (const float*)d_in[3];
    const float* Wg1 = (const float*)d_in[4];
    const float* bg1 = (const float*)d_in[5];
    const float* Wv1 = (const float*)d_in[6];
    const float* bv1 = (const float*)d_in[7];
    const float* Wo1 = (const float*)d_in[8];
    const float* bo1 = (const float*)d_in[9];
    const float* gp  = (const float*)d_in[10];
    const float* bp  = (const float*)d_in[11];
    const float* Win = (const float*)d_in[12];
    const float* Wou = (const float*)d_in[13];
    const float* Wg2 = (const float*)d_in[14];
    const float* bg2 = (const float*)d_in[15];
    const float* Wv2 = (const float*)d_in[16];
    const float* bv2 = (const float*)d_in[17];
    const float* Wo2 = (const float*)d_in[18];
    const float* bo2 = (const float*)d_in[19];
    const float* gl  = (const float*)d_in[20];
    const float* bl  = (const float*)d_in[21];
    float* out = (float*)d_out;

    cudaFuncSetAttribute(gemm_kernel<0>, cudaFuncAttributeMaxDynamicSharedMemorySize, DSMEM);
    cudaFuncSetAttribute(gemm_kernel<1>, cudaFuncAttributeMaxDynamicSharedMemorySize, DSMEM);
    cudaFuncSetAttribute(gemm_kernel<2>, cudaFuncAttributeMaxDynamicSharedMemorySize, DSMEM);

    float *gupre, *gcc;
    cudaGetSymbolAddress((void**)&gupre, g_upre);
    cudaGetSymbolAddress((void**)&gcc,   g_Cc);
    __half* gsh;
    cudaGetSymbolAddress((void**)&gsh, g_S);
    __nv_bfloat16 *a1h, *a1l, *hh, *hl, *lh, *ll, *x2h, *x2l, *x3h, *x3l;
    cudaGetSymbolAddress((void**)&a1h, g_A1h); cudaGetSymbolAddress((void**)&a1l, g_A1l);
    cudaGetSymbolAddress((void**)&hh,  g_Hh);  cudaGetSymbolAddress((void**)&hl,  g_Hl);
    cudaGetSymbolAddress((void**)&lh,  g_Lh);  cudaGetSymbolAddress((void**)&ll,  g_Ll);
    cudaGetSymbolAddress((void**)&x2h, g_X2h); cudaGetSymbolAddress((void**)&x2l, g_X2l);
    cudaGetSymbolAddress((void**)&x3h, g_X3h); cudaGetSymbolAddress((void**)&x3l, g_X3l);
    __nv_bfloat16 *w13h, *w13l, *wch, *wcl, *bo1h, *bo1l, *bioh, *biol, *b2h, *b2l, *bo2h, *bo2l;
    cudaGetSymbolAddress((void**)&w13h, gW13h); cudaGetSymbolAddress((void**)&w13l, gW13l);
    cudaGetSymbolAddress((void**)&wch,  gWch);  cudaGetSymbolAddress((void**)&wcl,  gWcl);
    cudaGetSymbolAddress((void**)&bo1h, gBo1h); cudaGetSymbolAddress((void**)&bo1l, gBo1l);
    cudaGetSymbolAddress((void**)&bioh, gBioh); cudaGetSymbolAddress((void**)&biol, gBiol);
    cudaGetSymbolAddress((void**)&b2h,  gB2h);  cudaGetSymbolAddress((void**)&b2l,  gB2l);
    cudaGetSymbolAddress((void**)&bo2h, gBo2h); cudaGetSymbolAddress((void**)&bo2l, gBo2l);

    // 1) prep
    zero_out_kernel<<<(NNODES * DDIM + 255) / 256, 256>>>();
    prep_weights_kernel<<<512, 256>>>(Wg1, Wv1, Wo1, Win, Wou, Wg2, Wv2, Wo2);
    prep_A1_kernel<<<(int)(((size_t)NR * 256 + 255) / 256), 256>>>(pair, local, nbrs);
    prep_L_kernel<<<(NNODES * DDIM + 255) / 256, 256>>>(local);

    // 2) Cc = local @ Wceni : [20000,128]x[128,512]
    gemm_kernel<0><<<dim3(4, 157), 256, DSMEM>>>(lh, ll, 128, NNODES, 128, wch, wcl,
                                                 gcc, 512, nullptr, nullptr, nullptr, nullptr, nullptr);
    // 3) H = gelu(A1@W13i + Cc + bg) * (… + bv) -> split bf16 Hh/Hl
    gemm_kernel<2><<<dim3(4, 2500), 256, DSMEM>>>(a1h, a1l, 256, NR, 256, w13h, w13l,
                                                  nullptr, 0, gcc, bg1, bv1, hh, hl);
    // 4) u_pre = H @ Bo1 : [320000,256]x[256,128] -> g_upre
    gemm_kernel<0><<<dim3(1, 2500), 256, DSMEM>>>(hh, hl, 256, NR, 256, bo1h, bo1l,
                                                  gupre, 128, nullptr, nullptr, nullptr, nullptr, nullptr);
    // 5) gates S = sigmoid(A1.pair @ [Win||Wou]) -> fp16 g_S
    gemm_kernel<1><<<dim3(2, 2500), 256, DSMEM>>>(a1h, a1l, 256, NR, 128, bioh, biol,
                                                  (float*)gsh, 256, nullptr, nullptr, nullptr, nullptr, nullptr);
    // 6) LN pair + residual pair output + store pu (adds bo1 inline)
    ln_pair_kernel<<<(NR + 7) / 8, 256>>>(pair, bo1, gp, bp, out);
    // 7) incoming sum + outgoing atomic scatter (fp16 gate reads)
    messages_kernel<<<NNODES, 128>>>(nbrs, mask);
    // 8) local features
    prep_X2_kernel<<<(NNODES * 384 + 255) / 256, 256>>>(local);
    // 9) X3 = fused local MLP hidden : [20000,384]x[384,512]
    gemm_kernel<2><<<dim3(4, 157), 256, DSMEM>>>(x2h, x2l, 384, NNODES, 384, b2h, b2l,
                                                 nullptr, 0, nullptr, bg2, bv2, x3h, x3l);
    // 10) u2_pre = X3 @ Bo2 -> g_upre (reuse)
    gemm_kernel<0><<<dim3(1, 157), 256, DSMEM>>>(x3h, x3l, 256, NNODES, 256, bo2h, bo2l,
                                                 gupre, 128, nullptr, nullptr, nullptr, nullptr, nullptr);
    // 11) LN local + residual local output
    ln_local_kernel<<<(NNODES + 7) / 8, 256>>>(local, bo2, gl, bl, out);
}